// round 1
// baseline (speedup 1.0000x reference)
#include <cuda_runtime.h>
#include <cuda_bf16.h>
#include <math_constants.h>

#define M_PTS 8192
#define C_DIM 64
#define KNN 20
#define HALF (M_PTS / 2)
#define QB 128          // queries per knn block
#define CT 128          // candidate tile

// ---------------- scratch (device globals; no allocation allowed) -------------
__device__ float g_sq[M_PTS];
__device__ float g_pd[2 * M_PTS * KNN];
__device__ int   g_pi[2 * M_PTS * KNN];
__device__ int   g_knn[M_PTS * KNN];

// ---------------- kernel 0: squared norms ------------------------------------
__global__ void sq_kernel(const float* __restrict__ pos) {
    int i = blockIdx.x * blockDim.x + threadIdx.x;
    if (i >= M_PTS) return;
    const float4* p4 = reinterpret_cast<const float4*>(pos + i * C_DIM);
    float s = 0.f;
#pragma unroll
    for (int v = 0; v < C_DIM / 4; v++) {
        float4 a = p4[v];
        s += a.x * a.x + a.y * a.y + a.z * a.z + a.w * a.w;
    }
    g_sq[i] = s;
}

// ---------------- kernel 1: partial KNN (candidate half per block.y) ----------
__global__ __launch_bounds__(QB) void knn_part(const float* __restrict__ pos) {
    const int tid = threadIdx.x;
    const int q = blockIdx.x * QB + tid;
    const int half = blockIdx.y;
    const int cand0 = half * HALF;
    const int cand1 = cand0 + HALF;

    const float4* pos4 = reinterpret_cast<const float4*>(pos);

    float4 qv[C_DIM / 4];
#pragma unroll
    for (int v = 0; v < C_DIM / 4; v++) qv[v] = pos4[q * (C_DIM / 4) + v];
    const float myq = g_sq[q];

    float bd[KNN];
    int bi[KNN];
#pragma unroll
    for (int i = 0; i < KNN; i++) { bd[i] = CUDART_INF_F; bi[i] = -1; }
    float cmax = CUDART_INF_F;
    int cpos = 0;

    __shared__ float4 tile[CT * (C_DIM / 4)];
    __shared__ float tsq[CT];

    for (int t0 = cand0; t0 < cand1; t0 += CT) {
        __syncthreads();
        // coalesced fill: tile flat layout == candidate-major float4
#pragma unroll
        for (int i = 0; i < (CT * (C_DIM / 4)) / QB; i++) {
            int fl = i * QB + tid;
            tile[fl] = pos4[t0 * (C_DIM / 4) + fl];
        }
        tsq[tid] = g_sq[t0 + tid];   // QB == CT
        __syncthreads();

        for (int j = 0; j < CT; j++) {
            float ax = 0.f, ay = 0.f, az = 0.f, aw = 0.f;
#pragma unroll
            for (int v = 0; v < C_DIM / 4; v++) {
                float4 cv = tile[j * (C_DIM / 4) + v];
                ax = fmaf(qv[v].x, cv.x, ax);
                ay = fmaf(qv[v].y, cv.y, ay);
                az = fmaf(qv[v].z, cv.z, az);
                aw = fmaf(qv[v].w, cv.w, aw);
            }
            float dot = (ax + ay) + (az + aw);
            float d = myq + tsq[j] - 2.0f * dot;
            if (d < cmax) {
                bd[cpos] = d;
                bi[cpos] = t0 + j;
                // rescan for new max
                float m = bd[0]; int mp = 0;
#pragma unroll
                for (int i = 1; i < KNN; i++) {
                    if (bd[i] > m) { m = bd[i]; mp = i; }
                }
                cmax = m; cpos = mp;
            }
        }
    }

    const int base = (half * M_PTS + q) * KNN;
#pragma unroll
    for (int i = 0; i < KNN; i++) { g_pd[base + i] = bd[i]; g_pi[base + i] = bi[i]; }
}

// ---------------- kernel 2: merge the two partial lists -----------------------
__global__ void knn_merge() {
    int q = blockIdx.x * blockDim.x + threadIdx.x;
    if (q >= M_PTS) return;
    float d[2 * KNN];
    int id[2 * KNN];
#pragma unroll
    for (int h = 0; h < 2; h++)
#pragma unroll
        for (int i = 0; i < KNN; i++) {
            d[h * KNN + i] = g_pd[(h * M_PTS + q) * KNN + i];
            id[h * KNN + i] = g_pi[(h * M_PTS + q) * KNN + i];
        }
    for (int s = 0; s < KNN; s++) {
        float bm = d[0]; int bp = 0;
        for (int i = 1; i < 2 * KNN; i++) {
            if (d[i] < bm || (d[i] == bm && id[i] < id[bp])) { bm = d[i]; bp = i; }
        }
        g_knn[q * KNN + s] = id[bp];
        d[bp] = CUDART_INF_F;
    }
}

// ---------------- kernel 3: EdgeConv MLP + max aggregation --------------------
// 2 queries per 128-thread block; weights staged in dynamic smem.
#define CONV_SMEM_FLOATS (128 * 64 + 64 * 64 + 2 * 64 + 2 * 128 + 2 * 64)
__global__ __launch_bounds__(128) void conv_kernel(
    const float* __restrict__ f,
    const float* __restrict__ W1, const float* __restrict__ b1,
    const float* __restrict__ W2, const float* __restrict__ b2,
    float* __restrict__ out)
{
    extern __shared__ float sm[];
    float* W1s  = sm;                    // [128][64]
    float* W2s  = W1s + 128 * 64;        // [64][64]
    float* fcs  = W2s + 64 * 64;         // [2][64]
    float* edge = fcs + 2 * 64;          // [2][128]
    float* h1s  = edge + 2 * 128;        // [2][64]

    const int tid = threadIdx.x;
    const int sub = tid >> 6;            // 0 or 1 (warps 0-1 / 2-3)
    const int o   = tid & 63;
    const int q   = blockIdx.x * 2 + sub;

    for (int i = tid; i < 128 * 64; i += 128) W1s[i] = W1[i];
    for (int i = tid; i < 64 * 64; i += 128)  W2s[i] = W2[i];
    fcs[sub * 64 + o] = f[q * 64 + o];
    const float bb1 = b1[o];
    const float bb2 = b2[o];
    float vmax = -CUDART_INF_F;
    __syncthreads();

    for (int k = 0; k < KNN; k++) {
        int nb = g_knn[q * KNN + k];
        float fn = f[nb * 64 + o];
        float c0 = fcs[sub * 64 + o];
        edge[sub * 128 + o]      = c0;
        edge[sub * 128 + 64 + o] = fn - c0;
        __syncthreads();

        float acc = bb1;
#pragma unroll
        for (int c = 0; c < 128; c++)
            acc = fmaf(edge[sub * 128 + c], W1s[c * 64 + o], acc);
        h1s[sub * 64 + o] = fmaxf(acc, 0.0f);
        __syncthreads();

        float a2 = bb2;
#pragma unroll
        for (int c = 0; c < 64; c++)
            a2 = fmaf(h1s[sub * 64 + c], W2s[c * 64 + o], a2);
        vmax = fmaxf(vmax, a2);
        __syncthreads();   // edge/h1 reused next iter
    }
    out[q * 64 + o] = vmax;
}

// ---------------- launch -------------------------------------------------------
extern "C" void kernel_launch(void* const* d_in, const int* in_sizes, int n_in,
                              void* d_out, int out_size)
{
    const float* pos  = (const float*)d_in[0];
    const float* feat = (const float*)d_in[1];
    const float* W1   = (const float*)d_in[2];
    const float* b1   = (const float*)d_in[3];
    const float* W2   = (const float*)d_in[4];
    const float* b2   = (const float*)d_in[5];
    float* out = (float*)d_out;

    sq_kernel<<<(M_PTS + 255) / 256, 256>>>(pos);

    dim3 kg(M_PTS / QB, 2);
    knn_part<<<kg, QB>>>(pos);

    knn_merge<<<(M_PTS + 255) / 256, 256>>>();

    cudaFuncSetAttribute(conv_kernel, cudaFuncAttributeMaxDynamicSharedMemorySize,
                         CONV_SMEM_FLOATS * (int)sizeof(float));
    conv_kernel<<<M_PTS / 2, 128, CONV_SMEM_FLOATS * (int)sizeof(float)>>>(
        feat, W1, b1, W2, b2, out);
}

// round 3
// speedup vs baseline: 1.5856x; 1.5856x over previous
#include <cuda_runtime.h>
#include <cuda_bf16.h>
#include <math_constants.h>

#define M_PTS 8192
#define C_DIM 64
#define KNN 20
#define NSPLIT 4
#define SPAN (M_PTS / NSPLIT)   // candidates per split
#define QB 128                  // queries (=threads) per knn block
#define CT 128                  // candidate tile

typedef unsigned long long ull;

// ---------------- scratch (device globals; no allocation allowed) -------------
__device__ float g_sq[M_PTS];
__device__ float g_pd[NSPLIT * M_PTS * KNN];
__device__ int   g_pi[NSPLIT * M_PTS * KNN];
__device__ int   g_knn[M_PTS * KNN];
__device__ float g_gb[M_PTS * C_DIM];   // Wb^T f
__device__ float g_u [M_PTS * C_DIM];   // b1 + Wa^T f - Wb^T f

// ---------------- f32x2 helpers ----------------------------------------------
__device__ __forceinline__ ull ffma2(ull a, ull b, ull c) {
    ull d;
    asm("fma.rn.f32x2 %0, %1, %2, %3;" : "=l"(d) : "l"(a), "l"(b), "l"(c));
    return d;
}
__device__ __forceinline__ ull pack2(float x, float y) {
    ull r;
    asm("mov.b64 %0, {%1, %2};" : "=l"(r) : "f"(x), "f"(y));
    return r;
}
__device__ __forceinline__ void unpack2(ull v, float& lo, float& hi) {
    asm("mov.b64 {%0, %1}, %2;" : "=f"(lo), "=f"(hi) : "l"(v));
}

// ---------------- kernel 0: squared norms ------------------------------------
__global__ void sq_kernel(const float* __restrict__ pos) {
    int i = blockIdx.x * blockDim.x + threadIdx.x;
    if (i >= M_PTS) return;
    const float4* p4 = reinterpret_cast<const float4*>(pos + i * C_DIM);
    float s = 0.f;
#pragma unroll
    for (int v = 0; v < C_DIM / 4; v++) {
        float4 a = p4[v];
        s += a.x * a.x + a.y * a.y + a.z * a.z + a.w * a.w;
    }
    g_sq[i] = s;
}

// ---------------- kernel 1: partial KNN (1/NSPLIT of candidates per block.y) --
__global__ __launch_bounds__(QB) void knn_part(const float* __restrict__ pos) {
    const int tid = threadIdx.x;
    const int q = blockIdx.x * QB + tid;
    const int split = blockIdx.y;
    const int cand0 = split * SPAN;
    const int cand1 = cand0 + SPAN;

    const float4* pos4 = reinterpret_cast<const float4*>(pos);

    // query packed as 32 x f32x2
    ull q2[C_DIM / 2];
#pragma unroll
    for (int v = 0; v < C_DIM / 4; v++) {
        float4 a = pos4[q * (C_DIM / 4) + v];
        q2[2 * v]     = pack2(a.x, a.y);
        q2[2 * v + 1] = pack2(a.z, a.w);
    }
    const float myq = g_sq[q];

    float bd[KNN];
    int bi[KNN];
#pragma unroll
    for (int i = 0; i < KNN; i++) { bd[i] = CUDART_INF_F; bi[i] = -1; }
    float cmax = CUDART_INF_F;
    int cpos = 0;

    __shared__ float4 tile[CT * (C_DIM / 4)];
    __shared__ float tsq[CT];

    for (int t0 = cand0; t0 < cand1; t0 += CT) {
        __syncthreads();
#pragma unroll
        for (int i = 0; i < (CT * (C_DIM / 4)) / QB; i++) {
            int fl = i * QB + tid;
            tile[fl] = pos4[t0 * (C_DIM / 4) + fl];
        }
        tsq[tid] = g_sq[t0 + tid];   // QB == CT
        __syncthreads();

        // 16 ulonglong2 (= 16 float4 = 64 floats) per candidate
        const ulonglong2* tl = reinterpret_cast<const ulonglong2*>(tile);
        for (int j = 0; j < CT; j++) {
            ull a0 = 0ULL, a1 = 0ULL, a2 = 0ULL, a3 = 0ULL;
#pragma unroll
            for (int v = 0; v < 8; v++) {
                ulonglong2 c0 = tl[j * 16 + 2 * v];
                ulonglong2 c1 = tl[j * 16 + 2 * v + 1];
                a0 = ffma2(q2[4 * v],     c0.x, a0);
                a1 = ffma2(q2[4 * v + 1], c0.y, a1);
                a2 = ffma2(q2[4 * v + 2], c1.x, a2);
                a3 = ffma2(q2[4 * v + 3], c1.y, a3);
            }
            float f0, f1, f2, f3, f4, f5, f6, f7;
            unpack2(a0, f0, f1);
            unpack2(a1, f2, f3);
            unpack2(a2, f4, f5);
            unpack2(a3, f6, f7);
            float dot = ((f0 + f1) + (f2 + f3)) + ((f4 + f5) + (f6 + f7));
            float d = fmaf(-2.0f, dot, myq + tsq[j]);
            if (d < cmax) {
                bd[cpos] = d;
                bi[cpos] = t0 + j;
                float m = bd[0]; int mp = 0;
#pragma unroll
                for (int i = 1; i < KNN; i++) {
                    if (bd[i] > m) { m = bd[i]; mp = i; }
                }
                cmax = m; cpos = mp;
            }
        }
    }

    const int base = (split * M_PTS + q) * KNN;
#pragma unroll
    for (int i = 0; i < KNN; i++) { g_pd[base + i] = bd[i]; g_pi[base + i] = bi[i]; }
}

// ---------------- kernel 2: merge the partial lists ---------------------------
__global__ __launch_bounds__(128) void knn_merge() {
    int q = blockIdx.x * blockDim.x + threadIdx.x;
    if (q >= M_PTS) return;
    float d[NSPLIT * KNN];
    int id[NSPLIT * KNN];
#pragma unroll
    for (int h = 0; h < NSPLIT; h++)
#pragma unroll
        for (int i = 0; i < KNN; i++) {
            d[h * KNN + i] = g_pd[(h * M_PTS + q) * KNN + i];
            id[h * KNN + i] = g_pi[(h * M_PTS + q) * KNN + i];
        }
    for (int s = 0; s < KNN; s++) {
        float bm = d[0]; int bp = 0;
        for (int i = 1; i < NSPLIT * KNN; i++) {
            if (d[i] < bm || (d[i] == bm && id[i] < id[bp])) { bm = d[i]; bp = i; }
        }
        g_knn[q * KNN + s] = id[bp];
        d[bp] = CUDART_INF_F;
    }
}

// ---------------- kernel 3: precompute u[p], g[p] -----------------------------
// h_k(q) = relu(u[q] + g[nbr_k]),  g[p] = Wb^T f_p,  u[q] = b1 + Wa^T f_q - g[q]
__global__ __launch_bounds__(256) void pre_kernel(
    const float* __restrict__ f,
    const float* __restrict__ W1, const float* __restrict__ b1)
{
    __shared__ float W1s[128 * 64];
    __shared__ float fs[32 * 64];
    const int tid = threadIdx.x;
    for (int i = tid; i < 128 * 64; i += 256) W1s[i] = W1[i];
    const int p0 = blockIdx.x * 32;
    for (int i = tid; i < 32 * 64; i += 256) fs[i] = f[p0 * 64 + i];
    __syncthreads();

    const int o = tid & 63;
    const int sub = tid >> 6;
    const float bb1 = b1[o];
    for (int pi = sub; pi < 32; pi += 4) {
        float u = bb1, g = 0.f;
#pragma unroll
        for (int c = 0; c < 64; c++) {
            float fv = fs[pi * 64 + c];
            u = fmaf(fv, W1s[c * 64 + o], u);
            g = fmaf(fv, W1s[(64 + c) * 64 + o], g);
        }
        g_gb[(p0 + pi) * 64 + o] = g;
        g_u [(p0 + pi) * 64 + o] = u - g;
    }
}

// ---------------- kernel 4: layer2 + max aggregation --------------------------
__global__ __launch_bounds__(128) void mlp_kernel(
    const float* __restrict__ W2, const float* __restrict__ b2,
    float* __restrict__ out)
{
    __shared__ float W2s[64 * 64];
    __shared__ float hs[2][KNN * 64];
    __shared__ int sidx[2][KNN];

    const int tid = threadIdx.x;
    const int sub = tid >> 6;
    const int o = tid & 63;
    const int q = blockIdx.x * 2 + sub;

    for (int i = tid; i < 64 * 64; i += 128) W2s[i] = W2[i];
    if (o < KNN) sidx[sub][o] = g_knn[q * KNN + o];
    __syncthreads();

    const float u = g_u[q * 64 + o];
#pragma unroll
    for (int k = 0; k < KNN; k++) {
        int nb = sidx[sub][k];
        hs[sub][k * 64 + o] = fmaxf(u + g_gb[nb * 64 + o], 0.f);
    }
    __syncthreads();

    float acc[KNN];
#pragma unroll
    for (int k = 0; k < KNN; k++) acc[k] = 0.f;
#pragma unroll
    for (int c = 0; c < 64; c++) {
        float w = W2s[c * 64 + o];
#pragma unroll
        for (int k = 0; k < KNN; k++)
            acc[k] = fmaf(hs[sub][k * 64 + c], w, acc[k]);
    }
    float v = acc[0];
#pragma unroll
    for (int k = 1; k < KNN; k++) v = fmaxf(v, acc[k]);
    out[q * 64 + o] = v + b2[o];
}

// ---------------- launch -------------------------------------------------------
extern "C" void kernel_launch(void* const* d_in, const int* in_sizes, int n_in,
                              void* d_out, int out_size)
{
    const float* pos  = (const float*)d_in[0];
    const float* feat = (const float*)d_in[1];
    const float* W1   = (const float*)d_in[2];
    const float* b1   = (const float*)d_in[3];
    const float* W2   = (const float*)d_in[4];
    const float* b2   = (const float*)d_in[5];
    float* out = (float*)d_out;

    sq_kernel<<<(M_PTS + 255) / 256, 256>>>(pos);

    dim3 kg(M_PTS / QB, NSPLIT);
    knn_part<<<kg, QB>>>(pos);

    knn_merge<<<(M_PTS + 127) / 128, 128>>>();

    pre_kernel<<<M_PTS / 32, 256>>>(feat, W1, b1);

    mlp_kernel<<<M_PTS / 2, 128>>>(W2, b2, out);
}